// round 8
// baseline (speedup 1.0000x reference)
#include <cuda_runtime.h>
#include <cuda_fp16.h>
#include <cstdint>

#define MAXN (1 << 17)          // 131072 >= N=100000
#define MAXE (1 << 21)          // 2097152 >= E=1600000

__device__ int   g_deg_out[MAXN];
__device__ int   g_deg_in [MAXN];
__device__ float g_dinv_out[MAXN];
__device__ float g_dinv_in [MAXN];
__device__ int   g_rows  [MAXN];       // segment start per node (atomic-reserved)
__device__ int   g_cursor[MAXN];       // fill cursor (seeded = start)
__device__ int   g_total;              // global reservation cursor
__device__ uint2 g_csr   [MAXE];       // packed {col, w_bits}
__device__ uint2 g_xwh[(size_t)MAXN * 16];  // x @ W^T in fp16 (row = 128B)

// ---------------------------------------------------------------------------
__global__ void k_zero(int N) {
    int i = blockIdx.x * blockDim.x + threadIdx.x;
    if (i < N) { g_deg_out[i] = 0; g_deg_in[i] = 0; }
    if (i == 0) g_total = 0;
}

__global__ void k_count_deg(const int* __restrict__ ei, int E) {
    int e = blockIdx.x * blockDim.x + threadIdx.x;
    if (e < E) {
        atomicAdd(&g_deg_out[ei[e]], 1);        // row = dst
        atomicAdd(&g_deg_in [ei[E + e]], 1);    // col = src
    }
}

// --- fused: dinv + CSR offset reservation (block scan + 1 atomic/block) ---
__global__ __launch_bounds__(256) void k_prep(int N) {
    int t = threadIdx.x;
    int i = blockIdx.x * 256 + t;
    int lane = t & 31, wid = t >> 5;

    int v = (i < N) ? g_deg_out[i] : 0;

    if (i < N) {
        int d_o = v;            if (d_o < 1) d_o = 1;
        int d_i = g_deg_in[i];  if (d_i < 1) d_i = 1;
        g_dinv_out[i] = rsqrtf((float)d_o);
        g_dinv_in [i] = rsqrtf((float)d_i);
    }

    // warp inclusive scan
    int s = v;
    #pragma unroll
    for (int off = 1; off < 32; off <<= 1) {
        int u = __shfl_up_sync(0xFFFFFFFFu, s, off);
        if (lane >= off) s += u;
    }
    __shared__ int wsum[8];
    __shared__ int blockbase;
    if (lane == 31) wsum[wid] = s;
    __syncthreads();
    int base = 0;
    #pragma unroll
    for (int w = 0; w < 8; w++)
        if (w < wid) base += wsum[w];

    if (t == 255) blockbase = atomicAdd(&g_total, base + s);  // block total
    __syncthreads();

    if (i < N) {
        int start = blockbase + base + s - v;    // exclusive within block + base
        g_rows  [i] = start;
        g_cursor[i] = start;
    }
}

// --- scatter edges into CSR: one packed 8B store per edge -----------------
__global__ void k_scatter(const int* __restrict__ ei, int E) {
    int e = blockIdx.x * blockDim.x + threadIdx.x;
    if (e >= E) return;
    int row = ei[e];
    int col = ei[E + e];
    int pos = atomicAdd(&g_cursor[row], 1);      // cursor pre-seeded = start
    uint2 p;
    p.x = (unsigned)col;
    p.y = __float_as_uint(g_dinv_in[col]);
    g_csr[pos] = p;
}

// --- x' = x @ W^T, output quantized to fp16 -------------------------------
__global__ __launch_bounds__(256) void k_gemm_xw(
    const float* __restrict__ x, const float* __restrict__ W, int N)
{
    __shared__ float4 Wt[64][16];      // Wt[i][og] = {W[4og+0..3][i]}
    __shared__ float  xs[64][68];      // row stride 68 floats (16B aligned)

    int tid = threadIdx.x;
    int rg  = tid >> 4;                // 0..15
    int og  = tid & 15;                // 0..15
    int row0 = blockIdx.x * 64;

    #pragma unroll
    for (int idx = tid; idx < 64 * 16; idx += 256) {
        int i = idx >> 4, g = idx & 15;
        float4 w;
        w.x = W[(4 * g + 0) * 64 + i];
        w.y = W[(4 * g + 1) * 64 + i];
        w.z = W[(4 * g + 2) * 64 + i];
        w.w = W[(4 * g + 3) * 64 + i];
        Wt[i][g] = w;
    }
    #pragma unroll
    for (int idx = tid; idx < 64 * 16; idx += 256) {
        int r = idx >> 4, c4 = idx & 15;
        int gr = row0 + r;
        float4 v = (gr < N) ? *(const float4*)(x + (size_t)gr * 64 + c4 * 4)
                            : make_float4(0.f, 0.f, 0.f, 0.f);
        *(float4*)&xs[r][c4 * 4] = v;
    }
    __syncthreads();

    float4 acc[4];
    #pragma unroll
    for (int j = 0; j < 4; j++) acc[j] = make_float4(0.f, 0.f, 0.f, 0.f);

    #pragma unroll
    for (int i = 0; i < 64; i += 4) {
        float4 w0 = Wt[i + 0][og];
        float4 w1 = Wt[i + 1][og];
        float4 w2 = Wt[i + 2][og];
        float4 w3 = Wt[i + 3][og];
        #pragma unroll
        for (int j = 0; j < 4; j++) {
            float4 xv = *(const float4*)&xs[rg * 4 + j][i];
            acc[j].x += xv.x * w0.x + xv.y * w1.x + xv.z * w2.x + xv.w * w3.x;
            acc[j].y += xv.x * w0.y + xv.y * w1.y + xv.z * w2.y + xv.w * w3.y;
            acc[j].z += xv.x * w0.z + xv.y * w1.z + xv.z * w2.z + xv.w * w3.z;
            acc[j].w += xv.x * w0.w + xv.y * w1.w + xv.z * w2.w + xv.w * w3.w;
        }
    }

    #pragma unroll
    for (int j = 0; j < 4; j++) {
        int r = row0 + rg * 4 + j;
        if (r < N) {
            __half2 h0 = __floats2half2_rn(acc[j].x, acc[j].y);
            __half2 h1 = __floats2half2_rn(acc[j].z, acc[j].w);
            uint2 u;
            u.x = reinterpret_cast<unsigned&>(h0);
            u.y = reinterpret_cast<unsigned&>(h1);
            g_xwh[(size_t)r * 16 + og] = u;
        }
    }
}

// --- CSR aggregation: fp16 gather, fp32 accumulate, fused bias ------------
// 16 lanes per dst node; each lane owns 4 features. Unroll 4 for MLP.
__global__ __launch_bounds__(256) void k_agg_csr(
    float* __restrict__ out, const float* __restrict__ b, int N)
{
    int t    = blockIdx.x * 256 + threadIdx.x;
    int n    = t >> 4;
    int lane = t & 15;
    if (n >= N) return;

    int start = g_rows[n];
    int deg   = g_deg_out[n];
    int end   = start + deg;

    float4 acc = make_float4(0.f, 0.f, 0.f, 0.f);
    int j = start;
    for (; j + 3 < end; j += 4) {
        uint2 e0 = g_csr[j    ];
        uint2 e1 = g_csr[j + 1];
        uint2 e2 = g_csr[j + 2];
        uint2 e3 = g_csr[j + 3];
        uint2 u0 = g_xwh[(size_t)e0.x * 16 + lane];
        uint2 u1 = g_xwh[(size_t)e1.x * 16 + lane];
        uint2 u2 = g_xwh[(size_t)e2.x * 16 + lane];
        uint2 u3 = g_xwh[(size_t)e3.x * 16 + lane];
        float w0 = __uint_as_float(e0.y);
        float w1 = __uint_as_float(e1.y);
        float w2 = __uint_as_float(e2.y);
        float w3 = __uint_as_float(e3.y);
        float2 a0 = __half22float2(reinterpret_cast<__half2&>(u0.x));
        float2 c0 = __half22float2(reinterpret_cast<__half2&>(u0.y));
        float2 a1 = __half22float2(reinterpret_cast<__half2&>(u1.x));
        float2 c1 = __half22float2(reinterpret_cast<__half2&>(u1.y));
        float2 a2 = __half22float2(reinterpret_cast<__half2&>(u2.x));
        float2 c2 = __half22float2(reinterpret_cast<__half2&>(u2.y));
        float2 a3 = __half22float2(reinterpret_cast<__half2&>(u3.x));
        float2 c3 = __half22float2(reinterpret_cast<__half2&>(u3.y));
        acc.x += w0 * a0.x + w1 * a1.x + w2 * a2.x + w3 * a3.x;
        acc.y += w0 * a0.y + w1 * a1.y + w2 * a2.y + w3 * a3.y;
        acc.z += w0 * c0.x + w1 * c1.x + w2 * c2.x + w3 * c3.x;
        acc.w += w0 * c0.y + w1 * c1.y + w2 * c2.y + w3 * c3.y;
    }
    for (; j < end; j++) {
        uint2 e0 = g_csr[j];
        uint2 u0 = g_xwh[(size_t)e0.x * 16 + lane];
        float w0 = __uint_as_float(e0.y);
        float2 a0 = __half22float2(reinterpret_cast<__half2&>(u0.x));
        float2 c0 = __half22float2(reinterpret_cast<__half2&>(u0.y));
        acc.x += w0 * a0.x;
        acc.y += w0 * a0.y;
        acc.z += w0 * c0.x;
        acc.w += w0 * c0.y;
    }

    float s = g_dinv_out[n];
    float4 bb = ((const float4*)b)[lane];
    float4 o;
    o.x = s * acc.x + bb.x;
    o.y = s * acc.y + bb.y;
    o.z = s * acc.z + bb.z;
    o.w = s * acc.w + bb.w;
    ((float4*)out)[(size_t)n * 16 + lane] = o;
}

// ---------------------------------------------------------------------------
extern "C" void kernel_launch(void* const* d_in, const int* in_sizes, int n_in,
                              void* d_out, int out_size)
{
    const float* x  = (const float*)d_in[0];
    const int*   ei = (const int*)d_in[1];     // int32 (JAX x64 disabled)
    const float* W  = (const float*)d_in[2];
    const float* b  = (const float*)d_in[3];
    float*       out = (float*)d_out;

    int N = in_sizes[0] / 64;
    int E = in_sizes[1] / 2;

    k_zero     <<<(N + 255) / 256, 256>>>(N);
    k_count_deg<<<(E + 255) / 256, 256>>>(ei, E);
    k_prep     <<<(N + 255) / 256, 256>>>(N);
    k_scatter  <<<(E + 255) / 256, 256>>>(ei, E);
    k_gemm_xw  <<<(N + 63) / 64, 256>>>(x, W, N);
    k_agg_csr  <<<(N * 16 + 255) / 256, 256>>>(out, b, N);
}

// round 9
// speedup vs baseline: 1.3283x; 1.3283x over previous
#include <cuda_runtime.h>
#include <cuda_fp16.h>
#include <cstdint>

#define MAXN (1 << 17)          // 131072 >= N=100000
#define MAXE (1 << 21)          // 2097152 >= E=1600000
#define NB_MAX 512              // max scan blocks

__device__ int   g_deg_out[MAXN];
__device__ int   g_deg_in [MAXN];
__device__ float g_dinv_out[MAXN];
__device__ float g_dinv_in [MAXN];
__device__ int   g_rows [MAXN + 1];    // exclusive CSR row starts
__device__ int   g_bsum [NB_MAX];
__device__ int   g_rank [MAXE];        // edge rank within dst segment (free from count)
__device__ uint2 g_csr  [MAXE];        // packed {col, w_bits}
__device__ uint2 g_xwh[(size_t)MAXN * 16];  // x @ W^T in fp16 (row = 128B)

// ---------------------------------------------------------------------------
__global__ void k_zero(int N) {
    int i = blockIdx.x * blockDim.x + threadIdx.x;
    if (i < N) { g_deg_out[i] = 0; g_deg_in[i] = 0; }
}

// count degrees; atomic return value IS the edge's rank in its dst segment.
__global__ void k_count_deg(const int* __restrict__ ei, int E) {
    int e = blockIdx.x * blockDim.x + threadIdx.x;
    if (e < E) {
        g_rank[e] = atomicAdd(&g_deg_out[ei[e]], 1);   // row = dst
        atomicAdd(&g_deg_in[ei[E + e]], 1);            // col = src
    }
}

// --- block-local exclusive scan of deg_out (shuffle-based) + dinv fused ---
__global__ __launch_bounds__(256) void k_scan1(int N) {
    int t = threadIdx.x;
    int i = blockIdx.x * 256 + t;
    int lane = t & 31, wid = t >> 5;

    int v = (i < N) ? g_deg_out[i] : 0;

    if (i < N) {                                 // fused dinv
        int d_o = v;            if (d_o < 1) d_o = 1;
        int d_i = g_deg_in[i];  if (d_i < 1) d_i = 1;
        g_dinv_out[i] = rsqrtf((float)d_o);
        g_dinv_in [i] = rsqrtf((float)d_i);
    }

    int s = v;                                   // warp inclusive scan
    #pragma unroll
    for (int off = 1; off < 32; off <<= 1) {
        int u = __shfl_up_sync(0xFFFFFFFFu, s, off);
        if (lane >= off) s += u;
    }
    __shared__ int wsum[8];
    if (lane == 31) wsum[wid] = s;
    __syncthreads();
    int base = 0;
    #pragma unroll
    for (int w = 0; w < 8; w++)
        if (w < wid) base += wsum[w];

    if (i < N) g_rows[i] = base + s - v;         // block-local exclusive
    if (t == 255) g_bsum[blockIdx.x] = base + s; // block total
}

// --- scan of block sums, 1 block (shuffle-based) --------------------------
__global__ __launch_bounds__(NB_MAX) void k_scan2(int nblocks) {
    int t = threadIdx.x;
    int lane = t & 31, wid = t >> 5;
    int v = (t < nblocks) ? g_bsum[t] : 0;
    int s = v;
    #pragma unroll
    for (int off = 1; off < 32; off <<= 1) {
        int u = __shfl_up_sync(0xFFFFFFFFu, s, off);
        if (lane >= off) s += u;
    }
    __shared__ int wsum[16];
    if (lane == 31) wsum[wid] = s;
    __syncthreads();
    int base = 0;
    #pragma unroll
    for (int w = 0; w < 16; w++)
        if (w < wid) base += wsum[w];
    g_bsum[t] = base + s - v;                    // exclusive
}

__global__ void k_scan3(int N, int E) {
    int i = blockIdx.x * blockDim.x + threadIdx.x;
    if (i < N) g_rows[i] += g_bsum[i >> 8];
    if (i == 0) g_rows[N] = E;
}

// --- scatter edges into CSR: NO atomics (rank precomputed by count) -------
__global__ void k_scatter(const int* __restrict__ ei, int E) {
    int e = blockIdx.x * blockDim.x + threadIdx.x;
    if (e >= E) return;
    int row = ei[e];
    int col = ei[E + e];
    int pos = g_rows[row] + g_rank[e];
    uint2 p;
    p.x = (unsigned)col;
    p.y = __float_as_uint(g_dinv_in[col]);
    g_csr[pos] = p;
}

// --- x' = x @ W^T, output quantized to fp16 -------------------------------
__global__ __launch_bounds__(256) void k_gemm_xw(
    const float* __restrict__ x, const float* __restrict__ W, int N)
{
    __shared__ float4 Wt[64][16];      // Wt[i][og] = {W[4og+0..3][i]}
    __shared__ float  xs[64][68];      // row stride 68 floats (16B aligned)

    int tid = threadIdx.x;
    int rg  = tid >> 4;                // 0..15
    int og  = tid & 15;                // 0..15
    int row0 = blockIdx.x * 64;

    #pragma unroll
    for (int idx = tid; idx < 64 * 16; idx += 256) {
        int i = idx >> 4, g = idx & 15;
        float4 w;
        w.x = W[(4 * g + 0) * 64 + i];
        w.y = W[(4 * g + 1) * 64 + i];
        w.z = W[(4 * g + 2) * 64 + i];
        w.w = W[(4 * g + 3) * 64 + i];
        Wt[i][g] = w;
    }
    #pragma unroll
    for (int idx = tid; idx < 64 * 16; idx += 256) {
        int r = idx >> 4, c4 = idx & 15;
        int gr = row0 + r;
        float4 v = (gr < N) ? *(const float4*)(x + (size_t)gr * 64 + c4 * 4)
                            : make_float4(0.f, 0.f, 0.f, 0.f);
        *(float4*)&xs[r][c4 * 4] = v;
    }
    __syncthreads();

    float4 acc[4];
    #pragma unroll
    for (int j = 0; j < 4; j++) acc[j] = make_float4(0.f, 0.f, 0.f, 0.f);

    #pragma unroll
    for (int i = 0; i < 64; i += 4) {
        float4 w0 = Wt[i + 0][og];
        float4 w1 = Wt[i + 1][og];
        float4 w2 = Wt[i + 2][og];
        float4 w3 = Wt[i + 3][og];
        #pragma unroll
        for (int j = 0; j < 4; j++) {
            float4 xv = *(const float4*)&xs[rg * 4 + j][i];
            acc[j].x += xv.x * w0.x + xv.y * w1.x + xv.z * w2.x + xv.w * w3.x;
            acc[j].y += xv.x * w0.y + xv.y * w1.y + xv.z * w2.y + xv.w * w3.y;
            acc[j].z += xv.x * w0.z + xv.y * w1.z + xv.z * w2.z + xv.w * w3.z;
            acc[j].w += xv.x * w0.w + xv.y * w1.w + xv.z * w2.w + xv.w * w3.w;
        }
    }

    #pragma unroll
    for (int j = 0; j < 4; j++) {
        int r = row0 + rg * 4 + j;
        if (r < N) {
            __half2 h0 = __floats2half2_rn(acc[j].x, acc[j].y);
            __half2 h1 = __floats2half2_rn(acc[j].z, acc[j].w);
            uint2 u;
            u.x = reinterpret_cast<unsigned&>(h0);
            u.y = reinterpret_cast<unsigned&>(h1);
            g_xwh[(size_t)r * 16 + og] = u;
        }
    }
}

// --- CSR aggregation: fp16 gather, fp32 accumulate, fused bias ------------
// 16 lanes per dst node; each lane owns 4 features. (R7 unroll-2 version.)
__global__ __launch_bounds__(256) void k_agg_csr(
    float* __restrict__ out, const float* __restrict__ b, int N)
{
    int t    = blockIdx.x * 256 + threadIdx.x;
    int n    = t >> 4;
    int lane = t & 15;
    if (n >= N) return;

    int start = g_rows[n];
    int end   = g_rows[n + 1];

    float4 acc = make_float4(0.f, 0.f, 0.f, 0.f);
    int j = start;
    for (; j + 1 < end; j += 2) {
        uint2 e0 = g_csr[j];
        uint2 e1 = g_csr[j + 1];
        uint2 u0 = g_xwh[(size_t)e0.x * 16 + lane];
        uint2 u1 = g_xwh[(size_t)e1.x * 16 + lane];
        float w0 = __uint_as_float(e0.y);
        float w1 = __uint_as_float(e1.y);
        float2 a0 = __half22float2(reinterpret_cast<__half2&>(u0.x));
        float2 b0 = __half22float2(reinterpret_cast<__half2&>(u0.y));
        float2 a1 = __half22float2(reinterpret_cast<__half2&>(u1.x));
        float2 b1 = __half22float2(reinterpret_cast<__half2&>(u1.y));
        acc.x += w0 * a0.x + w1 * a1.x;
        acc.y += w0 * a0.y + w1 * a1.y;
        acc.z += w0 * b0.x + w1 * b1.x;
        acc.w += w0 * b0.y + w1 * b1.y;
    }
    if (j < end) {
        uint2 e0 = g_csr[j];
        uint2 u0 = g_xwh[(size_t)e0.x * 16 + lane];
        float w0 = __uint_as_float(e0.y);
        float2 a0 = __half22float2(reinterpret_cast<__half2&>(u0.x));
        float2 b0 = __half22float2(reinterpret_cast<__half2&>(u0.y));
        acc.x += w0 * a0.x;
        acc.y += w0 * a0.y;
        acc.z += w0 * b0.x;
        acc.w += w0 * b0.y;
    }

    float s = g_dinv_out[n];
    float4 bb = ((const float4*)b)[lane];
    float4 o;
    o.x = s * acc.x + bb.x;
    o.y = s * acc.y + bb.y;
    o.z = s * acc.z + bb.z;
    o.w = s * acc.w + bb.w;
    ((float4*)out)[(size_t)n * 16 + lane] = o;
}

// ---------------------------------------------------------------------------
extern "C" void kernel_launch(void* const* d_in, const int* in_sizes, int n_in,
                              void* d_out, int out_size)
{
    const float* x  = (const float*)d_in[0];
    const int*   ei = (const int*)d_in[1];     // int32 (JAX x64 disabled)
    const float* W  = (const float*)d_in[2];
    const float* b  = (const float*)d_in[3];
    float*       out = (float*)d_out;

    int N = in_sizes[0] / 64;
    int E = in_sizes[1] / 2;
    int nblocks = (N + 255) / 256;

    k_zero     <<<(N + 255) / 256, 256>>>(N);
    k_count_deg<<<(E + 255) / 256, 256>>>(ei, E);
    k_scan1    <<<nblocks, 256>>>(N);
    k_scan2    <<<1, NB_MAX>>>(nblocks);
    k_scan3    <<<(N + 255) / 256, 256>>>(N, E);
    k_scatter  <<<(E + 255) / 256, 256>>>(ei, E);
    k_gemm_xw  <<<(N + 63) / 64, 256>>>(x, W, N);
    k_agg_csr  <<<(N * 16 + 255) / 256, 256>>>(out, b, N);
}

// round 13
// speedup vs baseline: 1.4595x; 1.0987x over previous
#include <cuda_runtime.h>
#include <cuda_fp16.h>
#include <cstdint>

#define MAXN (1 << 17)          // 131072 >= N=100000
#define MAXE (1 << 21)          // 2097152 >= E=1600000
#define NB_MAX 512              // max scan blocks

__device__ int   g_deg_out[MAXN];
__device__ int   g_deg_in [MAXN];
__device__ float g_dinv_out[MAXN];
__device__ float g_dinv_in [MAXN];
__device__ int   g_rows [MAXN];        // block-local exclusive row starts
__device__ int   g_bsum [NB_MAX];      // exclusive block offsets (added on use)
__device__ int   g_rank [MAXE];        // edge rank within dst segment
__device__ uint2 g_csr  [MAXE];        // packed {col, w_bits}
__device__ uint4 g_xwh[(size_t)MAXN * 8];   // x @ W^T fp16 (row = 8 uint4 = 128B)

// ---------------------------------------------------------------------------
__global__ void k_zero(int N) {
    int i = blockIdx.x * blockDim.x + threadIdx.x;
    if (i < N) { g_deg_out[i] = 0; g_deg_in[i] = 0; }
}

// count degrees; atomic return value IS the edge's rank in its dst segment.
__global__ void k_count_deg(const int* __restrict__ ei, int E) {
    int e = blockIdx.x * blockDim.x + threadIdx.x;
    if (e < E) {
        g_rank[e] = atomicAdd(&g_deg_out[ei[e]], 1);   // row = dst
        atomicAdd(&g_deg_in[ei[E + e]], 1);            // col = src
    }
}

// --- block-local exclusive scan of deg_out (shuffle) + dinv fused ---------
__global__ __launch_bounds__(256) void k_scan1(int N) {
    int t = threadIdx.x;
    int i = blockIdx.x * 256 + t;
    int lane = t & 31, wid = t >> 5;

    int v = (i < N) ? g_deg_out[i] : 0;

    if (i < N) {
        int d_o = v;            if (d_o < 1) d_o = 1;
        int d_i = g_deg_in[i];  if (d_i < 1) d_i = 1;
        g_dinv_out[i] = rsqrtf((float)d_o);
        g_dinv_in [i] = rsqrtf((float)d_i);
    }

    int s = v;
    #pragma unroll
    for (int off = 1; off < 32; off <<= 1) {
        int u = __shfl_up_sync(0xFFFFFFFFu, s, off);
        if (lane >= off) s += u;
    }
    __shared__ int wsum[8];
    if (lane == 31) wsum[wid] = s;
    __syncthreads();
    int base = 0;
    #pragma unroll
    for (int w = 0; w < 8; w++)
        if (w < wid) base += wsum[w];

    if (i < N) g_rows[i] = base + s - v;         // block-local exclusive
    if (t == 255) g_bsum[blockIdx.x] = base + s; // block total
}

// --- scan of block sums, 1 block (shuffle) --------------------------------
__global__ __launch_bounds__(NB_MAX) void k_scan2(int nblocks) {
    int t = threadIdx.x;
    int lane = t & 31, wid = t >> 5;
    int v = (t < nblocks) ? g_bsum[t] : 0;
    int s = v;
    #pragma unroll
    for (int off = 1; off < 32; off <<= 1) {
        int u = __shfl_up_sync(0xFFFFFFFFu, s, off);
        if (lane >= off) s += u;
    }
    __shared__ int wsum[16];
    if (lane == 31) wsum[wid] = s;
    __syncthreads();
    int base = 0;
    #pragma unroll
    for (int w = 0; w < 16; w++)
        if (w < wid) base += wsum[w];
    g_bsum[t] = base + s - v;                    // exclusive
}

// --- scatter: NO atomics; block offset folded in --------------------------
__global__ void k_scatter(const int* __restrict__ ei, int E) {
    int e = blockIdx.x * blockDim.x + threadIdx.x;
    if (e >= E) return;
    int row = ei[e];
    int col = ei[E + e];
    int pos = g_rows[row] + g_bsum[row >> 8] + g_rank[e];
    uint2 p;
    p.x = (unsigned)col;
    p.y = __float_as_uint(g_dinv_in[col]);
    g_csr[pos] = p;
}

// --- x' = x @ W^T, output quantized to fp16 -------------------------------
__global__ __launch_bounds__(256) void k_gemm_xw(
    const float* __restrict__ x, const float* __restrict__ W, int N)
{
    __shared__ float4 Wt[64][16];      // Wt[i][og] = {W[4og+0..3][i]}
    __shared__ float  xs[64][68];

    int tid = threadIdx.x;
    int rg  = tid >> 4;
    int og  = tid & 15;
    int row0 = blockIdx.x * 64;

    #pragma unroll
    for (int idx = tid; idx < 64 * 16; idx += 256) {
        int i = idx >> 4, g = idx & 15;
        float4 w;
        w.x = W[(4 * g + 0) * 64 + i];
        w.y = W[(4 * g + 1) * 64 + i];
        w.z = W[(4 * g + 2) * 64 + i];
        w.w = W[(4 * g + 3) * 64 + i];
        Wt[i][g] = w;
    }
    #pragma unroll
    for (int idx = tid; idx < 64 * 16; idx += 256) {
        int r = idx >> 4, c4 = idx & 15;
        int gr = row0 + r;
        float4 v = (gr < N) ? *(const float4*)(x + (size_t)gr * 64 + c4 * 4)
                            : make_float4(0.f, 0.f, 0.f, 0.f);
        *(float4*)&xs[r][c4 * 4] = v;
    }
    __syncthreads();

    float4 acc[4];
    #pragma unroll
    for (int j = 0; j < 4; j++) acc[j] = make_float4(0.f, 0.f, 0.f, 0.f);

    #pragma unroll
    for (int i = 0; i < 64; i += 4) {
        float4 w0 = Wt[i + 0][og];
        float4 w1 = Wt[i + 1][og];
        float4 w2 = Wt[i + 2][og];
        float4 w3 = Wt[i + 3][og];
        #pragma unroll
        for (int j = 0; j < 4; j++) {
            float4 xv = *(const float4*)&xs[rg * 4 + j][i];
            acc[j].x += xv.x * w0.x + xv.y * w1.x + xv.z * w2.x + xv.w * w3.x;
            acc[j].y += xv.x * w0.y + xv.y * w1.y + xv.z * w2.y + xv.w * w3.y;
            acc[j].z += xv.x * w0.z + xv.y * w1.z + xv.z * w2.z + xv.w * w3.z;
            acc[j].w += xv.x * w0.w + xv.y * w1.w + xv.z * w2.w + xv.w * w3.w;
        }
    }

    // store row as fp16: og-th uint2 pair packed into the row's 8 uint4
    #pragma unroll
    for (int j = 0; j < 4; j++) {
        int r = row0 + rg * 4 + j;
        if (r < N) {
            __half2 h0 = __floats2half2_rn(acc[j].x, acc[j].y);
            __half2 h1 = __floats2half2_rn(acc[j].z, acc[j].w);
            uint2 u;
            u.x = reinterpret_cast<unsigned&>(h0);
            u.y = reinterpret_cast<unsigned&>(h1);
            ((uint2*)g_xwh)[(size_t)r * 16 + og] = u;
        }
    }
}

// --- CSR aggregation: 8 lanes/node, uint4 (16B) gathers, unroll 4 ---------
__global__ __launch_bounds__(256) void k_agg_csr(
    float* __restrict__ out, const float* __restrict__ b, int N)
{
    int t    = blockIdx.x * 256 + threadIdx.x;
    int n    = t >> 3;
    int lane = t & 7;                  // owns features [lane*8, lane*8+8)
    if (n >= N) return;

    int start = g_rows[n] + g_bsum[n >> 8];
    int end   = start + g_deg_out[n];

    float2 acc0 = make_float2(0.f, 0.f);
    float2 acc1 = make_float2(0.f, 0.f);
    float2 acc2 = make_float2(0.f, 0.f);
    float2 acc3 = make_float2(0.f, 0.f);

    int j = start;
    for (; j + 3 < end; j += 4) {
        uint2 e0 = g_csr[j    ];
        uint2 e1 = g_csr[j + 1];
        uint2 e2 = g_csr[j + 2];
        uint2 e3 = g_csr[j + 3];
        uint4 u0 = g_xwh[(size_t)e0.x * 8 + lane];
        uint4 u1 = g_xwh[(size_t)e1.x * 8 + lane];
        uint4 u2 = g_xwh[(size_t)e2.x * 8 + lane];
        uint4 u3 = g_xwh[(size_t)e3.x * 8 + lane];
        float w0 = __uint_as_float(e0.y);
        float w1 = __uint_as_float(e1.y);
        float w2 = __uint_as_float(e2.y);
        float w3 = __uint_as_float(e3.y);
        {
            float2 f0 = __half22float2(reinterpret_cast<__half2&>(u0.x));
            float2 f1 = __half22float2(reinterpret_cast<__half2&>(u0.y));
            float2 f2 = __half22float2(reinterpret_cast<__half2&>(u0.z));
            float2 f3 = __half22float2(reinterpret_cast<__half2&>(u0.w));
            acc0.x += w0 * f0.x; acc0.y += w0 * f0.y;
            acc1.x += w0 * f1.x; acc1.y += w0 * f1.y;
            acc2.x += w0 * f2.x; acc2.y += w0 * f2.y;
            acc3.x += w0 * f3.x; acc3.y += w0 * f3.y;
        }
        {
            float2 f0 = __half22float2(reinterpret_cast<__half2&>(u1.x));
            float2 f1 = __half22float2(reinterpret_cast<__half2&>(u1.y));
            float2 f2 = __half22float2(reinterpret_cast<__half2&>(u1.z));
            float2 f3 = __half22float2(reinterpret_cast<__half2&>(u1.w));
            acc0.x += w1 * f0.x; acc0.y += w1 * f0.y;
            acc1.x += w1 * f1.x; acc1.y += w1 * f1.y;
            acc2.x += w1 * f2.x; acc2.y += w1 * f2.y;
            acc3.x += w1 * f3.x; acc3.y += w1 * f3.y;
        }
        {
            float2 f0 = __half22float2(reinterpret_cast<__half2&>(u2.x));
            float2 f1 = __half22float2(reinterpret_cast<__half2&>(u2.y));
            float2 f2 = __half22float2(reinterpret_cast<__half2&>(u2.z));
            float2 f3 = __half22float2(reinterpret_cast<__half2&>(u2.w));
            acc0.x += w2 * f0.x; acc0.y += w2 * f0.y;
            acc1.x += w2 * f1.x; acc1.y += w2 * f1.y;
            acc2.x += w2 * f2.x; acc2.y += w2 * f2.y;
            acc3.x += w2 * f3.x; acc3.y += w2 * f3.y;
        }
        {
            float2 f0 = __half22float2(reinterpret_cast<__half2&>(u3.x));
            float2 f1 = __half22float2(reinterpret_cast<__half2&>(u3.y));
            float2 f2 = __half22float2(reinterpret_cast<__half2&>(u3.z));
            float2 f3 = __half22float2(reinterpret_cast<__half2&>(u3.w));
            acc0.x += w3 * f0.x; acc0.y += w3 * f0.y;
            acc1.x += w3 * f1.x; acc1.y += w3 * f1.y;
            acc2.x += w3 * f2.x; acc2.y += w3 * f2.y;
            acc3.x += w3 * f3.x; acc3.y += w3 * f3.y;
        }
    }
    for (; j < end; j++) {
        uint2 e0 = g_csr[j];
        uint4 u0 = g_xwh[(size_t)e0.x * 8 + lane];
        float w0 = __uint_as_float(e0.y);
        float2 f0 = __half22float2(reinterpret_cast<__half2&>(u0.x));
        float2 f1 = __half22float2(reinterpret_cast<__half2&>(u0.y));
        float2 f2 = __half22float2(reinterpret_cast<__half2&>(u0.z));
        float2 f3 = __half22float2(reinterpret_cast<__half2&>(u0.w));
        acc0.x += w0 * f0.x; acc0.y += w0 * f0.y;
        acc1.x += w0 * f1.x; acc1.y += w0 * f1.y;
        acc2.x += w0 * f2.x; acc2.y += w0 * f2.y;
        acc3.x += w0 * f3.x; acc3.y += w0 * f3.y;
    }

    float s = g_dinv_out[n];
    // bias for features [lane*8, lane*8+8)
    float4 bb0 = ((const float4*)b)[lane * 2];
    float4 bb1 = ((const float4*)b)[lane * 2 + 1];
    float4 o0, o1;
    o0.x = s * acc0.x + bb0.x;
    o0.y = s * acc0.y + bb0.y;
    o0.z = s * acc1.x + bb0.z;
    o0.w = s * acc1.y + bb0.w;
    o1.x = s * acc2.x + bb1.x;
    o1.y = s * acc2.y + bb1.y;
    o1.z = s * acc3.x + bb1.z;
    o1.w = s * acc3.y + bb1.w;
    ((float4*)out)[(size_t)n * 16 + lane * 2    ] = o0;
    ((float4*)out)[(size_t)n * 16 + lane * 2 + 1] = o1;
}

// ---------------------------------------------------------------------------
extern "C" void kernel_launch(void* const* d_in, const int* in_sizes, int n_in,
                              void* d_out, int out_size)
{
    const float* x  = (const float*)d_in[0];
    const int*   ei = (const int*)d_in[1];     // int32 (JAX x64 disabled)
    const float* W  = (const float*)d_in[2];
    const float* b  = (const float*)d_in[3];
    float*       out = (float*)d_out;

    int N = in_sizes[0] / 64;
    int E = in_sizes[1] / 2;
    int nblocks = (N + 255) / 256;

    k_zero     <<<(N + 255) / 256, 256>>>(N);
    k_count_deg<<<(E + 255) / 256, 256>>>(ei, E);
    k_scan1    <<<nblocks, 256>>>(N);
    k_scan2    <<<1, NB_MAX>>>(nblocks);
    k_scatter  <<<(E + 255) / 256, 256>>>(ei, E);
    k_gemm_xw  <<<(N + 63) / 64, 256>>>(x, W, N);
    k_agg_csr  <<<(N * 8 + 255) / 256, 256>>>(out, b, N);
}

// round 16
// speedup vs baseline: 1.5237x; 1.0440x over previous
#include <cuda_runtime.h>
#include <cuda_fp16.h>
#include <cstdint>

#define MAXN (1 << 17)          // 131072 >= N=100000
#define MAXE (1 << 21)          // 2097152 >= E=1600000

__device__ int   g_deg_out[MAXN];
__device__ int   g_deg_in [MAXN];
__device__ float g_dinv_out[MAXN];
__device__ float g_dinv_in [MAXN];
__device__ int   g_rows [MAXN];        // absolute segment start per node
__device__ int   g_total;              // global reservation cursor
__device__ int   g_rank [MAXE];        // edge rank within dst segment
__device__ uint2 g_csr  [MAXE];        // packed {col, w_bits}
__device__ uint4 g_xwh[(size_t)MAXN * 8];   // x @ W^T fp16 (row = 8 uint4 = 128B)

// ---------------------------------------------------------------------------
__global__ void k_zero(int N) {
    int i = blockIdx.x * blockDim.x + threadIdx.x;
    if (i < N) { g_deg_out[i] = 0; g_deg_in[i] = 0; }
    if (i == 0) g_total = 0;
}

// --- fused: GEMM (blocks [0,nGemm)) + degree count (remaining blocks) -----
// Independent workloads co-scheduled across SMs: FFMA-bound GEMM overlaps
// latency-bound edge-index atomics.
__global__ __launch_bounds__(256) void k_gemm_count(
    const float* __restrict__ x, const float* __restrict__ W,
    const int* __restrict__ ei, int N, int E, int nGemm)
{
    __shared__ float4 Wt[64][16];      // gemm-only
    __shared__ float  xs[64][68];

    int tid = threadIdx.x;

    if (blockIdx.x >= nGemm) {
        // ---------------- degree count: 2 edges per thread (int2) ----------
        int bid = blockIdx.x - nGemm;
        int p = bid * 256 + tid;               // pair index
        int e = p * 2;
        if (e + 1 < E) {
            int2 d = *(const int2*)(ei + e);       // dst pair
            int2 s = *(const int2*)(ei + E + e);   // src pair
            int r0 = atomicAdd(&g_deg_out[d.x], 1);
            int r1 = atomicAdd(&g_deg_out[d.y], 1);
            *(int2*)(g_rank + e) = make_int2(r0, r1);
            atomicAdd(&g_deg_in[s.x], 1);
            atomicAdd(&g_deg_in[s.y], 1);
        } else if (e < E) {
            g_rank[e] = atomicAdd(&g_deg_out[ei[e]], 1);
            atomicAdd(&g_deg_in[ei[E + e]], 1);
        }
        return;
    }

    // ---------------- GEMM tile: x' = x @ W^T, fp16 output ----------------
    int rg  = tid >> 4;
    int og  = tid & 15;
    int row0 = blockIdx.x * 64;

    #pragma unroll
    for (int idx = tid; idx < 64 * 16; idx += 256) {
        int i = idx >> 4, g = idx & 15;
        float4 w;
        w.x = W[(4 * g + 0) * 64 + i];
        w.y = W[(4 * g + 1) * 64 + i];
        w.z = W[(4 * g + 2) * 64 + i];
        w.w = W[(4 * g + 3) * 64 + i];
        Wt[i][g] = w;
    }
    #pragma unroll
    for (int idx = tid; idx < 64 * 16; idx += 256) {
        int r = idx >> 4, c4 = idx & 15;
        int gr = row0 + r;
        float4 v = (gr < N) ? *(const float4*)(x + (size_t)gr * 64 + c4 * 4)
                            : make_float4(0.f, 0.f, 0.f, 0.f);
        *(float4*)&xs[r][c4 * 4] = v;
    }
    __syncthreads();

    float4 acc[4];
    #pragma unroll
    for (int j = 0; j < 4; j++) acc[j] = make_float4(0.f, 0.f, 0.f, 0.f);

    #pragma unroll
    for (int i = 0; i < 64; i += 4) {
        float4 w0 = Wt[i + 0][og];
        float4 w1 = Wt[i + 1][og];
        float4 w2 = Wt[i + 2][og];
        float4 w3 = Wt[i + 3][og];
        #pragma unroll
        for (int j = 0; j < 4; j++) {
            float4 xv = *(const float4*)&xs[rg * 4 + j][i];
            acc[j].x += xv.x * w0.x + xv.y * w1.x + xv.z * w2.x + xv.w * w3.x;
            acc[j].y += xv.x * w0.y + xv.y * w1.y + xv.z * w2.y + xv.w * w3.y;
            acc[j].z += xv.x * w0.z + xv.y * w1.z + xv.z * w2.z + xv.w * w3.z;
            acc[j].w += xv.x * w0.w + xv.y * w1.w + xv.z * w2.w + xv.w * w3.w;
        }
    }

    #pragma unroll
    for (int j = 0; j < 4; j++) {
        int r = row0 + rg * 4 + j;
        if (r < N) {
            __half2 h0 = __floats2half2_rn(acc[j].x, acc[j].y);
            __half2 h1 = __floats2half2_rn(acc[j].z, acc[j].w);
            uint2 u;
            u.x = reinterpret_cast<unsigned&>(h0);
            u.y = reinterpret_cast<unsigned&>(h1);
            ((uint2*)g_xwh)[(size_t)r * 16 + og] = u;
        }
    }
}

// --- prep: dinv + absolute CSR offsets (block scan + 1 atomic/block) ------
__global__ __launch_bounds__(256) void k_prep(int N) {
    int t = threadIdx.x;
    int i = blockIdx.x * 256 + t;
    int lane = t & 31, wid = t >> 5;

    int v = (i < N) ? g_deg_out[i] : 0;

    if (i < N) {
        int d_o = v;            if (d_o < 1) d_o = 1;
        int d_i = g_deg_in[i];  if (d_i < 1) d_i = 1;
        g_dinv_out[i] = rsqrtf((float)d_o);
        g_dinv_in [i] = rsqrtf((float)d_i);
    }

    int s = v;                                   // warp inclusive scan
    #pragma unroll
    for (int off = 1; off < 32; off <<= 1) {
        int u = __shfl_up_sync(0xFFFFFFFFu, s, off);
        if (lane >= off) s += u;
    }
    __shared__ int wsum[8];
    __shared__ int blockbase;
    if (lane == 31) wsum[wid] = s;
    __syncthreads();
    int base = 0;
    #pragma unroll
    for (int w = 0; w < 8; w++)
        if (w < wid) base += wsum[w];

    if (t == 255) blockbase = atomicAdd(&g_total, base + s);
    __syncthreads();

    if (i < N) g_rows[i] = blockbase + base + s - v;   // absolute start
}

// --- scatter: NO atomics (rank precomputed; absolute rows) ----------------
__global__ void k_scatter(const int* __restrict__ ei, int E) {
    int e = blockIdx.x * blockDim.x + threadIdx.x;
    if (e >= E) return;
    int row = ei[e];
    int col = ei[E + e];
    int pos = g_rows[row] + g_rank[e];
    uint2 p;
    p.x = (unsigned)col;
    p.y = __float_as_uint(g_dinv_in[col]);
    g_csr[pos] = p;
}

// --- CSR aggregation: 8 lanes/node, uint4 (16B) gathers, unroll 4 ---------
__global__ __launch_bounds__(256) void k_agg_csr(
    float* __restrict__ out, const float* __restrict__ b, int N)
{
    int t    = blockIdx.x * 256 + threadIdx.x;
    int n    = t >> 3;
    int lane = t & 7;                  // owns features [lane*8, lane*8+8)
    if (n >= N) return;

    int start = g_rows[n];
    int end   = start + g_deg_out[n];

    float2 acc0 = make_float2(0.f, 0.f);
    float2 acc1 = make_float2(0.f, 0.f);
    float2 acc2 = make_float2(0.f, 0.f);
    float2 acc3 = make_float2(0.f, 0.f);

    int j = start;
    for (; j + 3 < end; j += 4) {
        uint2 e0 = g_csr[j    ];
        uint2 e1 = g_csr[j + 1];
        uint2 e2 = g_csr[j + 2];
        uint2 e3 = g_csr[j + 3];
        uint4 u0 = g_xwh[(size_t)e0.x * 8 + lane];
        uint4 u1 = g_xwh[(size_t)e1.x * 8 + lane];
        uint4 u2 = g_xwh[(size_t)e2.x * 8 + lane];
        uint4 u3 = g_xwh[(size_t)e3.x * 8 + lane];
        float w0 = __uint_as_float(e0.y);
        float w1 = __uint_as_float(e1.y);
        float w2 = __uint_as_float(e2.y);
        float w3 = __uint_as_float(e3.y);
        {
            float2 f0 = __half22float2(reinterpret_cast<__half2&>(u0.x));
            float2 f1 = __half22float2(reinterpret_cast<__half2&>(u0.y));
            float2 f2 = __half22float2(reinterpret_cast<__half2&>(u0.z));
            float2 f3 = __half22float2(reinterpret_cast<__half2&>(u0.w));
            acc0.x += w0 * f0.x; acc0.y += w0 * f0.y;
            acc1.x += w0 * f1.x; acc1.y += w0 * f1.y;
            acc2.x += w0 * f2.x; acc2.y += w0 * f2.y;
            acc3.x += w0 * f3.x; acc3.y += w0 * f3.y;
        }
        {
            float2 f0 = __half22float2(reinterpret_cast<__half2&>(u1.x));
            float2 f1 = __half22float2(reinterpret_cast<__half2&>(u1.y));
            float2 f2 = __half22float2(reinterpret_cast<__half2&>(u1.z));
            float2 f3 = __half22float2(reinterpret_cast<__half2&>(u1.w));
            acc0.x += w1 * f0.x; acc0.y += w1 * f0.y;
            acc1.x += w1 * f1.x; acc1.y += w1 * f1.y;
            acc2.x += w1 * f2.x; acc2.y += w1 * f2.y;
            acc3.x += w1 * f3.x; acc3.y += w1 * f3.y;
        }
        {
            float2 f0 = __half22float2(reinterpret_cast<__half2&>(u2.x));
            float2 f1 = __half22float2(reinterpret_cast<__half2&>(u2.y));
            float2 f2 = __half22float2(reinterpret_cast<__half2&>(u2.z));
            float2 f3 = __half22float2(reinterpret_cast<__half2&>(u2.w));
            acc0.x += w2 * f0.x; acc0.y += w2 * f0.y;
            acc1.x += w2 * f1.x; acc1.y += w2 * f1.y;
            acc2.x += w2 * f2.x; acc2.y += w2 * f2.y;
            acc3.x += w2 * f3.x; acc3.y += w2 * f3.y;
        }
        {
            float2 f0 = __half22float2(reinterpret_cast<__half2&>(u3.x));
            float2 f1 = __half22float2(reinterpret_cast<__half2&>(u3.y));
            float2 f2 = __half22float2(reinterpret_cast<__half2&>(u3.z));
            float2 f3 = __half22float2(reinterpret_cast<__half2&>(u3.w));
            acc0.x += w3 * f0.x; acc0.y += w3 * f0.y;
            acc1.x += w3 * f1.x; acc1.y += w3 * f1.y;
            acc2.x += w3 * f2.x; acc2.y += w3 * f2.y;
            acc3.x += w3 * f3.x; acc3.y += w3 * f3.y;
        }
    }
    for (; j < end; j++) {
        uint2 e0 = g_csr[j];
        uint4 u0 = g_xwh[(size_t)e0.x * 8 + lane];
        float w0 = __uint_as_float(e0.y);
        float2 f0 = __half22float2(reinterpret_cast<__half2&>(u0.x));
        float2 f1 = __half22float2(reinterpret_cast<__half2&>(u0.y));
        float2 f2 = __half22float2(reinterpret_cast<__half2&>(u0.z));
        float2 f3 = __half22float2(reinterpret_cast<__half2&>(u0.w));
        acc0.x += w0 * f0.x; acc0.y += w0 * f0.y;
        acc1.x += w0 * f1.x; acc1.y += w0 * f1.y;
        acc2.x += w0 * f2.x; acc2.y += w0 * f2.y;
        acc3.x += w0 * f3.x; acc3.y += w0 * f3.y;
    }

    float s = g_dinv_out[n];
    float4 bb0 = ((const float4*)b)[lane * 2];
    float4 bb1 = ((const float4*)b)[lane * 2 + 1];
    float4 o0, o1;
    o0.x = s * acc0.x + bb0.x;
    o0.y = s * acc0.y + bb0.y;
    o0.z = s * acc1.x + bb0.z;
    o0.w = s * acc1.y + bb0.w;
    o1.x = s * acc2.x + bb1.x;
    o1.y = s * acc2.y + bb1.y;
    o1.z = s * acc3.x + bb1.z;
    o1.w = s * acc3.y + bb1.w;
    ((float4*)out)[(size_t)n * 16 + lane * 2    ] = o0;
    ((float4*)out)[(size_t)n * 16 + lane * 2 + 1] = o1;
}

// ---------------------------------------------------------------------------
extern "C" void kernel_launch(void* const* d_in, const int* in_sizes, int n_in,
                              void* d_out, int out_size)
{
    const float* x  = (const float*)d_in[0];
    const int*   ei = (const int*)d_in[1];     // int32 (JAX x64 disabled)
    const float* W  = (const float*)d_in[2];
    const float* b  = (const float*)d_in[3];
    float*       out = (float*)d_out;

    int N = in_sizes[0] / 64;
    int E = in_sizes[1] / 2;

    int nGemm  = (N + 63) / 64;
    int nCount = ((E + 1) / 2 + 255) / 256;    // 2 edges per thread

    k_zero      <<<(N + 255) / 256, 256>>>(N);
    k_gemm_count<<<nGemm + nCount, 256>>>(x, W, ei, N, E, nGemm);
    k_prep      <<<(N + 255) / 256, 256>>>(N);
    k_scatter   <<<(E + 255) / 256, 256>>>(ei, E);
    k_agg_csr   <<<(N * 8 + 255) / 256, 256>>>(out, b, N);
}

// round 17
// speedup vs baseline: 1.6097x; 1.0564x over previous
#include <cuda_runtime.h>
#include <cuda_fp16.h>
#include <cstdint>

#define MAXN (1 << 17)          // 131072 >= N=100000
#define MAXE (1 << 21)          // 2097152 >= E=1600000

__device__ int   g_deg_out[MAXN];
__device__ int   g_deg_in [MAXN];
__device__ float g_dinv_out[MAXN];
__device__ float g_dinv_in [MAXN];
__device__ int   g_rows [MAXN];        // absolute segment start per node
__device__ int   g_total;              // global reservation cursor
__device__ int   g_rank [MAXE];        // edge rank within dst segment
__device__ int   g_csr  [MAXE];        // col only (dinv_in folded into x'')
__device__ uint4 g_xwh[(size_t)MAXN * 8];   // dinv_in[r] * (x @ W^T)[r], fp16

// ---------------------------------------------------------------------------
__global__ void k_zero(int N) {
    int i = blockIdx.x * blockDim.x + threadIdx.x;
    if (i < N) { g_deg_out[i] = 0; g_deg_in[i] = 0; }
    if (i == 0) g_total = 0;
}

// --- degree count: 2 edges per thread (int2); rank from atomic return -----
__global__ void k_count_deg(const int* __restrict__ ei, int E) {
    int p = blockIdx.x * blockDim.x + threadIdx.x;
    int e = p * 2;
    if (e + 1 < E) {
        int2 d = *(const int2*)(ei + e);       // dst pair
        int2 s = *(const int2*)(ei + E + e);   // src pair
        int r0 = atomicAdd(&g_deg_out[d.x], 1);
        int r1 = atomicAdd(&g_deg_out[d.y], 1);
        *(int2*)(g_rank + e) = make_int2(r0, r1);
        atomicAdd(&g_deg_in[s.x], 1);
        atomicAdd(&g_deg_in[s.y], 1);
    } else if (e < E) {
        g_rank[e] = atomicAdd(&g_deg_out[ei[e]], 1);
        atomicAdd(&g_deg_in[ei[E + e]], 1);
    }
}

// --- prep: dinv + absolute CSR offsets (block scan + 1 atomic/block) ------
__global__ __launch_bounds__(256) void k_prep(int N) {
    int t = threadIdx.x;
    int i = blockIdx.x * 256 + t;
    int lane = t & 31, wid = t >> 5;

    int v = (i < N) ? g_deg_out[i] : 0;

    if (i < N) {
        int d_o = v;            if (d_o < 1) d_o = 1;
        int d_i = g_deg_in[i];  if (d_i < 1) d_i = 1;
        g_dinv_out[i] = rsqrtf((float)d_o);
        g_dinv_in [i] = rsqrtf((float)d_i);
    }

    int s = v;                                   // warp inclusive scan
    #pragma unroll
    for (int off = 1; off < 32; off <<= 1) {
        int u = __shfl_up_sync(0xFFFFFFFFu, s, off);
        if (lane >= off) s += u;
    }
    __shared__ int wsum[8];
    __shared__ int blockbase;
    if (lane == 31) wsum[wid] = s;
    __syncthreads();
    int base = 0;
    #pragma unroll
    for (int w = 0; w < 8; w++)
        if (w < wid) base += wsum[w];

    if (t == 255) blockbase = atomicAdd(&g_total, base + s);
    __syncthreads();

    if (i < N) g_rows[i] = blockbase + base + s - v;   // absolute start
}

// --- fused: GEMM (blocks [0,nGemm)) + scatter (remaining blocks) ----------
// Both depend only on k_prep; FFMA-bound GEMM overlaps LTS-bound scatter.
__global__ __launch_bounds__(256) void k_gemm_scatter(
    const float* __restrict__ x, const float* __restrict__ W,
    const int* __restrict__ ei, int N, int E, int nGemm)
{
    __shared__ float4 Wt[64][16];      // gemm-only
    __shared__ float  xs[64][68];

    int tid = threadIdx.x;

    if (blockIdx.x >= nGemm) {
        // ------------- scatter: 2 edges/thread, 4B col-only stores --------
        int p = (blockIdx.x - nGemm) * 256 + tid;
        int e = p * 2;
        if (e + 1 < E) {
            int2 d = *(const int2*)(ei + e);       // dst pair
            int2 s = *(const int2*)(ei + E + e);   // src pair
            int2 r = *(const int2*)(g_rank + e);
            g_csr[g_rows[d.x] + r.x] = s.x;
            g_csr[g_rows[d.y] + r.y] = s.y;
        } else if (e < E) {
            g_csr[g_rows[ei[e]] + g_rank[e]] = ei[E + e];
        }
        return;
    }

    // ------ GEMM tile: x'' = dinv_in[r] * (x @ W^T)[r], fp16 output -------
    int rg  = tid >> 4;
    int og  = tid & 15;
    int row0 = blockIdx.x * 64;

    #pragma unroll
    for (int idx = tid; idx < 64 * 16; idx += 256) {
        int i = idx >> 4, g = idx & 15;
        float4 w;
        w.x = W[(4 * g + 0) * 64 + i];
        w.y = W[(4 * g + 1) * 64 + i];
        w.z = W[(4 * g + 2) * 64 + i];
        w.w = W[(4 * g + 3) * 64 + i];
        Wt[i][g] = w;
    }
    #pragma unroll
    for (int idx = tid; idx < 64 * 16; idx += 256) {
        int r = idx >> 4, c4 = idx & 15;
        int gr = row0 + r;
        float4 v = (gr < N) ? *(const float4*)(x + (size_t)gr * 64 + c4 * 4)
                            : make_float4(0.f, 0.f, 0.f, 0.f);
        *(float4*)&xs[r][c4 * 4] = v;
    }
    __syncthreads();

    float4 acc[4];
    #pragma unroll
    for (int j = 0; j < 4; j++) acc[j] = make_float4(0.f, 0.f, 0.f, 0.f);

    #pragma unroll
    for (int i = 0; i < 64; i += 4) {
        float4 w0 = Wt[i + 0][og];
        float4 w1 = Wt[i + 1][og];
        float4 w2 = Wt[i + 2][og];
        float4 w3 = Wt[i + 3][og];
        #pragma unroll
        for (int j = 0; j < 4; j++) {
            float4 xv = *(const float4*)&xs[rg * 4 + j][i];
            acc[j].x += xv.x * w0.x + xv.y * w1.x + xv.z * w2.x + xv.w * w3.x;
            acc[j].y += xv.x * w0.y + xv.y * w1.y + xv.z * w2.y + xv.w * w3.y;
            acc[j].z += xv.x * w0.z + xv.y * w1.z + xv.z * w2.z + xv.w * w3.z;
            acc[j].w += xv.x * w0.w + xv.y * w1.w + xv.z * w2.w + xv.w * w3.w;
        }
    }

    #pragma unroll
    for (int j = 0; j < 4; j++) {
        int r = row0 + rg * 4 + j;
        if (r < N) {
            float di = g_dinv_in[r];
            __half2 h0 = __floats2half2_rn(di * acc[j].x, di * acc[j].y);
            __half2 h1 = __floats2half2_rn(di * acc[j].z, di * acc[j].w);
            uint2 u;
            u.x = reinterpret_cast<unsigned&>(h0);
            u.y = reinterpret_cast<unsigned&>(h1);
            ((uint2*)g_xwh)[(size_t)r * 16 + og] = u;
        }
    }
}

// --- CSR aggregation: 8 lanes/node, uint4 (16B) gathers, unroll 4 ---------
__global__ __launch_bounds__(256) void k_agg_csr(
    float* __restrict__ out, const float* __restrict__ b, int N)
{
    int t    = blockIdx.x * 256 + threadIdx.x;
    int n    = t >> 3;
    int lane = t & 7;                  // owns features [lane*8, lane*8+8)
    if (n >= N) return;

    int start = g_rows[n];
    int end   = start + g_deg_out[n];

    float2 acc0 = make_float2(0.f, 0.f);
    float2 acc1 = make_float2(0.f, 0.f);
    float2 acc2 = make_float2(0.f, 0.f);
    float2 acc3 = make_float2(0.f, 0.f);

    int j = start;
    for (; j + 3 < end; j += 4) {
        int c0 = g_csr[j    ];
        int c1 = g_csr[j + 1];
        int c2 = g_csr[j + 2];
        int c3 = g_csr[j + 3];
        uint4 u0 = g_xwh[(size_t)c0 * 8 + lane];
        uint4 u1 = g_xwh[(size_t)c1 * 8 + lane];
        uint4 u2 = g_xwh[(size_t)c2 * 8 + lane];
        uint4 u3 = g_xwh[(size_t)c3 * 8 + lane];
        {
            float2 f0 = __half22float2(reinterpret_cast<__half2&>(u0.x));
            float2 f1 = __half22float2(reinterpret_cast<__half2&>(u0.y));
            float2 f2 = __half22float2(reinterpret_cast<__half2&>(u0.z));
            float2 f3 = __half22float2(reinterpret_cast<__half2&>(u0.w));
            acc0.x += f0.x; acc0.y += f0.y;
            acc1.x += f1.x; acc1.y += f1.y;
            acc2.x += f2.x; acc2.y += f2.y;
            acc3.x += f3.x; acc3.y += f3.y;
        }
        {
            float2 f0 = __half22float2(reinterpret_cast<__half2&>(u1.x));
            float2 f1 = __half22float2(reinterpret_cast<__half2&>(u1.y));
            float2 f2 = __half22float2(reinterpret_cast<__half2&>(u1.z));
            float2 f3 = __half22float2(reinterpret_cast<__half2&>(u1.w));
            acc0.x += f0.x; acc0.y += f0.y;
            acc1.x += f1.x; acc1.y += f1.y;
            acc2.x += f2.x; acc2.y += f2.y;
            acc3.x += f3.x; acc3.y += f3.y;
        }
        {
            float2 f0 = __half22float2(reinterpret_cast<__half2&>(u2.x));
            float2 f1 = __half22float2(reinterpret_cast<__half2&>(u2.y));
            float2 f2 = __half22float2(reinterpret_cast<__half2&>(u2.z));
            float2 f3 = __half22float2(reinterpret_cast<__half2&>(u2.w));
            acc0.x += f0.x; acc0.y += f0.y;
            acc1.x += f1.x; acc1.y += f1.y;
            acc2.x += f2.x; acc2.y += f2.y;
            acc3.x += f3.x; acc3.y += f3.y;
        }
        {
            float2 f0 = __half22float2(reinterpret_cast<__half2&>(u3.x));
            float2 f1 = __half22float2(reinterpret_cast<__half2&>(u3.y));
            float2 f2 = __half22float2(reinterpret_cast<__half2&>(u3.z));
            float2 f3 = __half22float2(reinterpret_cast<__half2&>(u3.w));
            acc0.x += f0.x; acc0.y += f0.y;
            acc1.x += f1.x; acc1.y += f1.y;
            acc2.x += f2.x; acc2.y += f2.y;
            acc3.x += f3.x; acc3.y += f3.y;
        }
    }
    for (; j < end; j++) {
        int c0 = g_csr[j];
        uint4 u0 = g_xwh[(size_t)c0 * 8 + lane];
        float2 f0 = __half22float2(reinterpret_cast<__half2&>(u0.x));
        float2 f1 = __half22float2(reinterpret_cast<__half2&>(u0.y));
        float2 f2 = __half22float2(reinterpret_cast<__half2&>(u0.z));
        float2 f3 = __half22float2(reinterpret_cast<__half2&>(u0.w));
        acc0.x += f0.x; acc0.y += f0.y;
        acc1.x += f1.x; acc1.y += f1.y;
        acc2.x += f2.x; acc2.y += f2.y;
        acc3.x += f3.x; acc3.y += f3.y;
    }

    float s = g_dinv_out[n];
    float4 bb0 = ((const float4*)b)[lane * 2];
    float4 bb1 = ((const float4*)b)[lane * 2 + 1];
    float4 o0, o1;
    o0.x = s * acc0.x + bb0.x;
    o0.y = s * acc0.y + bb0.y;
    o0.z = s * acc1.x + bb0.z;
    o0.w = s * acc1.y + bb0.w;
    o1.x = s * acc2.x + bb1.x;
    o1.y = s * acc2.y + bb1.y;
    o1.z = s * acc3.x + bb1.z;
    o1.w = s * acc3.y + bb1.w;
    ((float4*)out)[(size_t)n * 16 + lane * 2    ] = o0;
    ((float4*)out)[(size_t)n * 16 + lane * 2 + 1] = o1;
}

// ---------------------------------------------------------------------------
extern "C" void kernel_launch(void* const* d_in, const int* in_sizes, int n_in,
                              void* d_out, int out_size)
{
    const float* x  = (const float*)d_in[0];
    const int*   ei = (const int*)d_in[1];     // int32 (JAX x64 disabled)
    const float* W  = (const float*)d_in[2];
    const float* b  = (const float*)d_in[3];
    float*       out = (float*)d_out;

    int N = in_sizes[0] / 64;
    int E = in_sizes[1] / 2;

    int nGemm    = (N + 63) / 64;
    int nScatter = ((E + 1) / 2 + 255) / 256;  // 2 edges per thread
    int nCount   = nScatter;

    k_zero        <<<(N + 255) / 256, 256>>>(N);
    k_count_deg   <<<nCount, 256>>>(ei, E);
    k_prep        <<<(N + 255) / 256, 256>>>(N);
    k_gemm_scatter<<<nGemm + nScatter, 256>>>(x, W, ei, N, E, nGemm);
    k_agg_csr     <<<(N * 8 + 255) / 256, 256>>>(out, b, N);
}